// round 2
// baseline (speedup 1.0000x reference)
#include <cuda_runtime.h>
#include <math.h>

// Problem constants (fixed per metadata):
//   d_in[0] points     f32 [2,6144,3]
//   d_in[1] embeddings f32 [2,6144,32]
//   d_in[2] leaf_mask  i32 [2,6144]
//   d_in[3] W1 f32 [64,32], d_in[4] b1 [32], d_in[5] W2 [32,32], d_in[6] b2 [32]
//   out f32 [2,6144,32]
#define BB 2
#define NN 6144
#define DD 32
#define JS 16          // number of j-slices per batch
#define CAP 16         // max list entries per (point, slice); E[count] ~ 0.8
#define ITILE 512      // compacted-i points per pairwise block (128 thr x 4)

// ---------------- device scratch (static, zero-init; every consumed cell is
// rewritten each launch or provably 0-stable -> deterministic replays) -------
__device__ float          g_norm[BB * NN];            // clamped |e_i|
__device__ float4         g_cpts[BB * NN];            // compacted leaf pts (x,y,z,pn)
__device__ unsigned short g_cidx[BB * NN];            // slot -> original index
__device__ int            g_slot[BB * NN];            // original -> slot (-1 if non-leaf)
__device__ int            g_nleaf[BB];                // leaf count per batch
__device__ unsigned char  g_nbcnt[BB * NN * JS];      // nb count per (slot, slice)
__device__ unsigned short g_list [BB * NN * JS * CAP];// nb j-indices (orig), j-ascending

// ---------------- K1: embedding norms ---------------------------------------
__global__ void k_norm(const float* __restrict__ emb) {
    int idx = blockIdx.x * blockDim.x + threadIdx.x;
    if (idx >= BB * NN) return;
    const float4* e = reinterpret_cast<const float4*>(emb) + (size_t)idx * 8;
    float s = 0.f;
#pragma unroll
    for (int k = 0; k < 8; k++) {
        float4 v = e[k];
        s += v.x * v.x; s += v.y * v.y; s += v.z * v.z; s += v.w * v.w;
    }
    g_norm[idx] = fmaxf(sqrtf(s), 1e-8f);
}

// ---------------- K2: leaf compaction (one block per batch) ------------------
__global__ __launch_bounds__(1024) void k_compact(const float* __restrict__ pts,
                                                  const int* __restrict__ leaf) {
    int b = blockIdx.x;
    int t = threadIdx.x;
    const int E = NN / 1024;  // 6 elements per thread
    __shared__ int wtot[32];
    int lm[E];
    int cnt = 0;
    int base = b * NN + t * E;
#pragma unroll
    for (int e = 0; e < E; e++) { lm[e] = (leaf[base + e] > 0) ? 1 : 0; cnt += lm[e]; }
    int lane = t & 31, w = t >> 5;
    int v = cnt;
#pragma unroll
    for (int o = 1; o < 32; o <<= 1) {
        int u = __shfl_up_sync(0xffffffffu, v, o);
        if (lane >= o) v += u;
    }
    if (lane == 31) wtot[w] = v;
    __syncthreads();
    if (w == 0) {
        int sv = wtot[lane];
#pragma unroll
        for (int o = 1; o < 32; o <<= 1) {
            int u = __shfl_up_sync(0xffffffffu, sv, o);
            if (lane >= o) sv += u;
        }
        wtot[lane] = sv;
    }
    __syncthreads();
    int pos = v - cnt + (w ? wtot[w - 1] : 0);  // exclusive prefix
#pragma unroll
    for (int e = 0; e < E; e++) {
        int i = t * E + e;
        if (lm[e]) {
            float x = pts[(size_t)(base + e) * 3 + 0];
            float y = pts[(size_t)(base + e) * 3 + 1];
            float z = pts[(size_t)(base + e) * 3 + 2];
            // pn = sum(p*p): squares rounded separately, summed left-to-right
            float pn = __fadd_rn(__fadd_rn(__fmul_rn(x, x), __fmul_rn(y, y)),
                                 __fmul_rn(z, z));
            g_cpts[b * NN + pos] = make_float4(x, y, z, pn);
            g_cidx[b * NN + pos] = (unsigned short)i;
            g_slot[base + e] = pos;
            pos++;
        } else {
            g_slot[base + e] = -1;
        }
    }
    if (t == 0) g_nleaf[b] = wtot[31];
}

// ---------------- K3: pairwise radius pass over compacted leaf points --------
__global__ __launch_bounds__(128) void k_pairs() {
    int b = blockIdx.z, s = blockIdx.y;
    int nl = g_nleaf[b];
    int cbase = blockIdx.x * ITILE;
    if (cbase >= nl) return;
    int L = (nl + JS - 1) / JS;
    int j0 = s * L;
    int j1 = min(j0 + L, nl);
    int len = j1 - j0;  // <= 384

    __shared__ float4         smp[384];
    __shared__ unsigned short smj[384];
    for (int k = threadIdx.x; k < len; k += 128) {
        smp[k] = g_cpts[b * NN + j0 + k];
        smj[k] = g_cidx[b * NN + j0 + k];
    }
    __syncthreads();

    const float R2 = (float)(0.03 * 0.03);

    float4 P[4];
    int    cn[4];
    size_t lbase[4];
#pragma unroll
    for (int k = 0; k < 4; k++) {
        int c = cbase + threadIdx.x + 128 * k;
        // inactive lanes get pn=+huge -> d2 always > R2, never pass
        P[k] = (c < nl) ? g_cpts[b * NN + c] : make_float4(0.f, 0.f, 0.f, 3.0e38f);
        cn[k] = 0;
        lbase[k] = (((size_t)(b * NN + c)) * JS + (size_t)s) * CAP;
    }

#pragma unroll 4
    for (int j = 0; j < len; j++) {
        float4 q = smp[j];
        bool pass[4];
#pragma unroll
        for (int k = 0; k < 4; k++) {
            // dot = fma chain; d2 = round((pni+pnj) - 2*dot)  [matches reference]
            float dot = fmaf(P[k].z, q.z, fmaf(P[k].y, q.y, __fmul_rn(P[k].x, q.x)));
            float d2  = fmaf(-2.f, dot, __fadd_rn(P[k].w, q.w));
            pass[k] = d2 < R2;
        }
        if (pass[0] | pass[1] | pass[2] | pass[3]) {
            unsigned short jj = smj[j];
#pragma unroll
            for (int k = 0; k < 4; k++) {
                if (pass[k]) {
                    if (cn[k] < CAP) g_list[lbase[k] + cn[k]] = jj;
                    cn[k]++;
                }
            }
        }
    }
#pragma unroll
    for (int k = 0; k < 4; k++) {
        int c = cbase + threadIdx.x + 128 * k;
        g_nbcnt[((size_t)(b * NN + c)) * JS + s] =
            (unsigned char)(cn[k] > 255 ? 255 : cn[k]);
    }
}

// ---------------- K4: sparse sims + MLP + output (one warp per point) --------
__global__ __launch_bounds__(256) void k_final(const float* __restrict__ emb,
                                               const float* __restrict__ W1,
                                               const float* __restrict__ b1,
                                               const float* __restrict__ W2,
                                               const float* __restrict__ b2,
                                               float* __restrict__ out) {
    __shared__ float sW1[64 * 32], sW2[32 * 32], sb1[32], sb2[32];
    int t = threadIdx.x;
    for (int k = t; k < 2048; k += 256) sW1[k] = W1[k];
    for (int k = t; k < 1024; k += 256) sW2[k] = W2[k];
    if (t < 32) { sb1[t] = b1[t]; sb2[t] = b2[t]; }
    __syncthreads();

    int w    = blockIdx.x * 8 + (t >> 5);  // global point id 0..B*N-1
    int lane = t & 31;                     // embedding dim
    int b    = w / NN;

    float ei  = emb[(size_t)w * DD + lane];
    float val = ei;

    int slot = g_slot[w];
    if (g_nleaf[b] >= 10 && slot >= 0) {
        float ni  = g_norm[w];
        float thr = __fmul_rn(0.7f, ni);
        float acc = 0.f;
        int   cns = 0, cnb = 0;
        const unsigned char*  cp = &g_nbcnt[((size_t)(b * NN + slot)) * JS];
        const unsigned short* lp = &g_list [((size_t)(b * NN + slot)) * JS * CAP];
        for (int s = 0; s < JS; s++) {
            int cs = cp[s];
            cnb += cs;
            int ne = min(cs, CAP);
            for (int e = 0; e < ne; e++) {
                int   j  = lp[s * CAP + e];
                float ej = emb[((size_t)(b * NN + j)) * DD + lane];
                float p  = __fmul_rn(ei, ej);
                p += __shfl_xor_sync(0xffffffffu, p, 16);
                p += __shfl_xor_sync(0xffffffffu, p, 8);
                p += __shfl_xor_sync(0xffffffffu, p, 4);
                p += __shfl_xor_sync(0xffffffffu, p, 2);
                p += __shfl_xor_sync(0xffffffffu, p, 1);
                float nj = g_norm[b * NN + j];
                if (p > __fmul_rn(thr, nj)) { acc += ej; cns++; }
            }
        }
        if (cnb > 1 && cns > 0) {
            float mean = acc / (float)cns;
            float h = sb1[lane];
#pragma unroll
            for (int k = 0; k < 32; k++)
                h = fmaf(__shfl_sync(0xffffffffu, ei, k), sW1[k * DD + lane], h);
#pragma unroll
            for (int k = 0; k < 32; k++)
                h = fmaf(__shfl_sync(0xffffffffu, mean, k), sW1[(k + 32) * DD + lane], h);
            h = fmaxf(h, 0.f);
            float o = sb2[lane];
#pragma unroll
            for (int k = 0; k < 32; k++)
                o = fmaf(__shfl_sync(0xffffffffu, h, k), sW2[k * DD + lane], o);
            val = o;
        }
    }
    out[(size_t)w * DD + lane] = val;
}

// ---------------- launch -----------------------------------------------------
extern "C" void kernel_launch(void* const* d_in, const int* in_sizes, int n_in,
                              void* d_out, int out_size) {
    const float* points = (const float*)d_in[0];
    const float* emb    = (const float*)d_in[1];
    const int*   leaf   = (const int*)d_in[2];
    const float* W1     = (const float*)d_in[3];
    const float* b1     = (const float*)d_in[4];
    const float* W2     = (const float*)d_in[5];
    const float* b2     = (const float*)d_in[6];
    float*       out    = (float*)d_out;

    k_norm<<<(BB * NN + 255) / 256, 256>>>(emb);
    k_compact<<<BB, 1024>>>(points, leaf);
    dim3 g2((NN + ITILE - 1) / ITILE, JS, BB);
    k_pairs<<<g2, 128>>>();
    k_final<<<(BB * NN) / 8, 256>>>(emb, W1, b1, W2, b2, out);
}